// round 7
// baseline (speedup 1.0000x reference)
#include <cuda_runtime.h>
#include <cuda_bf16.h>
#include <cstdint>

#define MAX_N 100000
#define MAX_E 1250000
#define D 64
#define SCAN_BLK 2048
#define MAX_SCAN_BLKS 64

// ---------------- fused kernel smem layout (bytes) ----------------
// A chunks: 128 rows x 72 bf16 (144B padded stride) = 18432B each.
// B mats:   64 rows x 72 bf16 = 9216B each (Wl_hi, Wl_lo, Wr_hi, Wr_lo).
#define SM_AMH  0
#define SM_AML  18432
#define SM_AXH  36864
#define SM_AXL  55296
#define SM_B    73728
#define SM_BIAS 110592
#define GEMM_SMEM 110848
#define APAD 144   // bytes per padded A/B row

// Scratch (device globals; no allocation allowed).
__device__ float g_h[MAX_N * D];
__device__ int   g_cnt[MAX_N];
__device__ int   g_off[MAX_N];
__device__ int   g_pos[MAX_N];
__device__ int   g_csr[MAX_E];
__device__ int   g_blk[MAX_SCAN_BLKS];
// Weight images: [layer][Wl_hi | Wl_lo | Wr_hi | Wr_lo][n*64+k] bf16, B[n][k] = W[k][n]
__device__ unsigned short g_wt[2][4 * 4096];

// ---------------------------------------------------------------------------
__device__ __forceinline__ uint32_t smem_u32(const void* p) {
    uint32_t a;
    asm("{ .reg .u64 t; cvta.to.shared.u64 t, %1; cvt.u32.u64 %0, t; }"
        : "=r"(a) : "l"(p));
    return a;
}
__device__ __forceinline__ void ldsm_x4(uint32_t& r0, uint32_t& r1,
                                        uint32_t& r2, uint32_t& r3,
                                        uint32_t addr) {
    asm volatile("ldmatrix.sync.aligned.m8n8.x4.shared.b16 {%0,%1,%2,%3}, [%4];"
                 : "=r"(r0), "=r"(r1), "=r"(r2), "=r"(r3) : "r"(addr));
}
__device__ __forceinline__ void mma_bf16(float* c, const uint32_t* a,
                                         uint32_t b0, uint32_t b1) {
    asm volatile("mma.sync.aligned.m16n8k16.row.col.f32.bf16.bf16.f32 "
                 "{%0,%1,%2,%3}, {%4,%5,%6,%7}, {%8,%9}, {%0,%1,%2,%3};"
                 : "+f"(c[0]), "+f"(c[1]), "+f"(c[2]), "+f"(c[3])
                 : "r"(a[0]), "r"(a[1]), "r"(a[2]), "r"(a[3]),
                   "r"(b0), "r"(b1));
}
__device__ __forceinline__ void split2(float v, unsigned short& h, unsigned short& l) {
    __nv_bfloat16 hb = __float2bfloat16(v);
    float r = v - __bfloat162float(hb);
    __nv_bfloat16 lb = __float2bfloat16(r);
    h = *(unsigned short*)&hb;
    l = *(unsigned short*)&lb;
}
__device__ __forceinline__ uint2 pack_hi4(unsigned short h0, unsigned short h1,
                                          unsigned short h2, unsigned short h3) {
    return make_uint2((uint32_t)h0 | ((uint32_t)h1 << 16),
                      (uint32_t)h2 | ((uint32_t)h3 << 16));
}

// ---------------------------------------------------------------------------
// CSR build (unchanged from R2)
// ---------------------------------------------------------------------------
__global__ void zero_int_kernel(int* __restrict__ p, int n) {
    int i = blockIdx.x * blockDim.x + threadIdx.x;
    if (i < n) p[i] = 0;
}
__global__ void hist_kernel(const int* __restrict__ ei, int* __restrict__ cnt, int E) {
    int e = blockIdx.x * blockDim.x + threadIdx.x;
    if (e < E) atomicAdd(&cnt[ei[E + e]], 1);
}
__global__ __launch_bounds__(256)
void scan_k1(const int* __restrict__ cnt, int* __restrict__ off,
             int* __restrict__ blk, int n) {
    __shared__ int warp_excl[8];
    int t = threadIdx.x;
    int lane = t & 31, w = t >> 5;
    int base = blockIdx.x * SCAN_BLK + t * 8;
    int v[8];
    int s = 0;
#pragma unroll
    for (int q = 0; q < 8; q++) {
        int idx = base + q;
        v[q] = (idx < n) ? cnt[idx] : 0;
        s += v[q];
    }
    int ps = s;
#pragma unroll
    for (int d = 1; d < 32; d <<= 1) {
        int o = __shfl_up_sync(0xffffffffu, ps, d);
        if (lane >= d) ps += o;
    }
    if (lane == 31) warp_excl[w] = ps;
    __syncthreads();
    if (w == 0 && lane < 8) {
        int ws = warp_excl[lane];
        int pw = ws;
#pragma unroll
        for (int d = 1; d < 8; d <<= 1) {
            int o = __shfl_up_sync(0xffu, pw, d);
            if (lane >= d) pw += o;
        }
        warp_excl[lane] = pw - ws;
    }
    __syncthreads();
    int excl = warp_excl[w] + (ps - s);
    int run = excl;
#pragma unroll
    for (int q = 0; q < 8; q++) {
        int idx = base + q;
        if (idx < n) off[idx] = run;
        run += v[q];
    }
    if (t == 255) blk[blockIdx.x] = excl + s;
}
__global__ void scan_k2(int* __restrict__ blk, int nb) {
    __shared__ int sm[MAX_SCAN_BLKS];
    int t = threadIdx.x;
    int v = (t < nb) ? blk[t] : 0;
    sm[t] = v;
    __syncthreads();
    for (int d = 1; d < MAX_SCAN_BLKS; d <<= 1) {
        int o = (t >= d) ? sm[t - d] : 0;
        __syncthreads();
        sm[t] += o;
        __syncthreads();
    }
    if (t < nb) blk[t] = sm[t] - v;
}
__global__ void scan_k3(int* __restrict__ off, const int* __restrict__ blk,
                        int* __restrict__ pos, int n) {
    int i = blockIdx.x * blockDim.x + threadIdx.x;
    if (i < n) {
        int o = off[i] + blk[i >> 11];
        off[i] = o;
        pos[i] = o;
    }
}
__global__ void fill_kernel(const int* __restrict__ ei, int* __restrict__ pos,
                            int* __restrict__ csr, int E) {
    int e = blockIdx.x * blockDim.x + threadIdx.x;
    if (e < E) {
        int dst = ei[E + e];
        int p = atomicAdd(&pos[dst], 1);
        csr[p] = ei[e];
    }
}

// ---------------------------------------------------------------------------
// Weight prep: B[n][k] = W[k][n], hi/lo bf16 split, into g_wt.
// ---------------------------------------------------------------------------
__global__ void prep_weights(const float* __restrict__ Wl1,
                             const float* __restrict__ Wr1,
                             const float* __restrict__ Wl2,
                             const float* __restrict__ Wr2) {
    int i = blockIdx.x * blockDim.x + threadIdx.x;   // 0 .. 16383
    if (i >= 2 * 2 * 64 * 64) return;
    int k = i & 63;
    int nn = (i >> 6) & 63;
    int mat = (i >> 12) & 1;     // 0 = Wl, 1 = Wr
    int layer = (i >> 13) & 1;
    const float* W = (layer == 0) ? (mat == 0 ? Wl1 : Wr1)
                                  : (mat == 0 ? Wl2 : Wr2);
    float v = W[k * 64 + nn];
    unsigned short h, l;
    split2(v, h, l);
    g_wt[layer][(mat * 2 + 0) * 4096 + nn * 64 + k] = h;
    g_wt[layer][(mat * 2 + 1) * 4096 + nn * 64 + k] = l;
}

// ---------------------------------------------------------------------------
// Fused layer: aggregate (CSR gather + mean) + transform (HMMA split GEMM).
//   out = act( mean(x, CSR) @ Wl + bl + x @ Wr )
// CTA = 128 nodes, 256 threads (8 warps).
// Aggregate phase: 8 passes x 16 nodes; 16 threads/node, each owns one
// float4 chunk of the row; accumulates neighbors in registers, splits
// fp32 -> bf16 hi/lo, stores straight into MMA A staging buffers.
// ---------------------------------------------------------------------------
__global__ __launch_bounds__(256)
void fused_layer(const float* __restrict__ xin,
                 const int* __restrict__ off,
                 const int* __restrict__ cnt,
                 const int* __restrict__ csr,
                 const unsigned short* __restrict__ wt,
                 const float* __restrict__ bl,
                 float* __restrict__ out,
                 int n, int do_relu) {
    extern __shared__ char smem[];
    uint32_t sb = smem_u32(smem);
    int t = threadIdx.x;
    int wid = t >> 5;
    int lane = t & 31;
    int base = blockIdx.x * 128;

    // --- Stage weights (pad 128B rows -> 144B stride) + bias ---
    {
        int mat = t >> 6;          // 0..3
        int nrow = t & 63;
        const uint4* src = (const uint4*)(wt + mat * 4096 + nrow * 64);
        uint4* dst = (uint4*)(smem + SM_B + mat * 9216 + nrow * APAD);
#pragma unroll
        for (int q = 0; q < 8; q++) dst[q] = src[q];
    }
    if (t < 64) ((float*)(smem + SM_BIAS))[t] = bl[t];

    // --- Fused aggregate + A staging: 8 passes x 16 nodes ---
    const float4* x4 = (const float4*)xin;
    int j = t & 15;                 // float4 chunk within row
    int grp = t >> 4;               // node-within-pass
#pragma unroll
    for (int pass = 0; pass < 8; pass++) {
        int local = pass * 16 + grp;
        int node = base + local;
        float4 a0 = make_float4(0.f, 0.f, 0.f, 0.f);
        float4 a1 = make_float4(0.f, 0.f, 0.f, 0.f);
        float4 xv = a0;
        if (node < n) {
            int s = off[node];
            int c = cnt[node];
            int e = s + c;
            int i = s;
            for (; i + 2 <= e; i += 2) {
                int s0 = csr[i];
                int s1 = csr[i + 1];
                float4 v0 = x4[(size_t)s0 * 16 + j];
                float4 v1 = x4[(size_t)s1 * 16 + j];
                a0.x += v0.x; a0.y += v0.y; a0.z += v0.z; a0.w += v0.w;
                a1.x += v1.x; a1.y += v1.y; a1.z += v1.z; a1.w += v1.w;
            }
            if (i < e) {
                float4 v = x4[(size_t)csr[i] * 16 + j];
                a0.x += v.x; a0.y += v.y; a0.z += v.z; a0.w += v.w;
            }
            float inv = 1.0f / fmaxf((float)c, 1.0f);
            a0.x = (a0.x + a1.x) * inv;
            a0.y = (a0.y + a1.y) * inv;
            a0.z = (a0.z + a1.z) * inv;
            a0.w = (a0.w + a1.w) * inv;
            xv = x4[(size_t)node * 16 + j];
        }
        // split + store into MMA staging
        int boff = local * APAD + j * 8;
        unsigned short h0, h1, h2, h3, l0, l1, l2, l3;
        split2(a0.x, h0, l0); split2(a0.y, h1, l1);
        split2(a0.z, h2, l2); split2(a0.w, h3, l3);
        *(uint2*)(smem + SM_AMH + boff) = pack_hi4(h0, h1, h2, h3);
        *(uint2*)(smem + SM_AML + boff) = pack_hi4(l0, l1, l2, l3);
        split2(xv.x, h0, l0); split2(xv.y, h1, l1);
        split2(xv.z, h2, l2); split2(xv.w, h3, l3);
        *(uint2*)(smem + SM_AXH + boff) = pack_hi4(h0, h1, h2, h3);
        *(uint2*)(smem + SM_AXL + boff) = pack_hi4(l0, l1, l2, l3);
    }
    __syncthreads();

    // --- MMA mainloop: 6 products x 4 ksteps x 8 n-tiles ---
    const uint32_t paOff[6] = {SM_AMH, SM_AMH, SM_AML, SM_AXH, SM_AXH, SM_AXL};
    const uint32_t pbOff[6] = {SM_B + 0 * 9216, SM_B + 1 * 9216, SM_B + 0 * 9216,
                               SM_B + 2 * 9216, SM_B + 3 * 9216, SM_B + 2 * 9216};

    int wrow = wid * 16;
    uint32_t a_row = wrow + (lane & 7) + ((lane >> 3) & 1) * 8;
    uint32_t a_colb = ((lane >> 4) * 8) * 2;
    uint32_t a_base_off = a_row * APAD + a_colb;
    uint32_t b_row = ((lane >> 4) * 8 + (lane & 7));
    uint32_t b_colb = (((lane >> 3) & 1) * 8) * 2;
    uint32_t b_base_off = b_row * APAD + b_colb;

    float acc[8][4];
#pragma unroll
    for (int jj = 0; jj < 8; jj++)
#pragma unroll
        for (int q = 0; q < 4; q++) acc[jj][q] = 0.f;

#pragma unroll
    for (int p = 0; p < 6; p++) {
        uint32_t aBase = sb + paOff[p] + a_base_off;
        uint32_t bBase = sb + pbOff[p] + b_base_off;
#pragma unroll
        for (int k = 0; k < 4; k++) {
            uint32_t a[4];
            ldsm_x4(a[0], a[1], a[2], a[3], aBase + k * 32);
#pragma unroll
            for (int jj = 0; jj < 4; jj++) {
                uint32_t b0, b1, b2, b3;
                ldsm_x4(b0, b1, b2, b3, bBase + jj * 16 * APAD + k * 32);
                mma_bf16(acc[2 * jj],     a, b0, b1);
                mma_bf16(acc[2 * jj + 1], a, b2, b3);
            }
        }
    }

    // --- Epilogue: bias + relu + store ---
    const float* bias = (const float*)(smem + SM_BIAS);
    int r0 = base + wrow + (lane >> 2);
    int r1 = r0 + 8;
    int ctig = 2 * (lane & 3);
#pragma unroll
    for (int jj = 0; jj < 8; jj++) {
        int col = 8 * jj + ctig;
        float bx = bias[col], by = bias[col + 1];
        float2 v0 = make_float2(acc[jj][0] + bx, acc[jj][1] + by);
        float2 v1 = make_float2(acc[jj][2] + bx, acc[jj][3] + by);
        if (do_relu) {
            v0.x = fmaxf(v0.x, 0.f); v0.y = fmaxf(v0.y, 0.f);
            v1.x = fmaxf(v1.x, 0.f); v1.y = fmaxf(v1.y, 0.f);
        }
        if (r0 < n) *(float2*)&out[(size_t)r0 * 64 + col] = v0;
        if (r1 < n) *(float2*)&out[(size_t)r1 * 64 + col] = v1;
    }
}

// ---------------------------------------------------------------------------
extern "C" void kernel_launch(void* const* d_in, const int* in_sizes, int n_in,
                              void* d_out, int out_size) {
    const float* x   = (const float*)d_in[0];
    const int*   ei  = (const int*)d_in[1];
    const float* Wl1 = (const float*)d_in[2];
    const float* bl1 = (const float*)d_in[3];
    const float* Wr1 = (const float*)d_in[4];
    const float* Wl2 = (const float*)d_in[5];
    const float* bl2 = (const float*)d_in[6];
    const float* Wr2 = (const float*)d_in[7];
    float* out = (float*)d_out;

    int N = in_sizes[0] / D;   // 100000
    int E = in_sizes[1] / 2;   // 1250000

    float* h;
    int *cnt, *off, *pos, *csr, *blk;
    unsigned short* wt;
    cudaGetSymbolAddress((void**)&h,   g_h);
    cudaGetSymbolAddress((void**)&cnt, g_cnt);
    cudaGetSymbolAddress((void**)&off, g_off);
    cudaGetSymbolAddress((void**)&pos, g_pos);
    cudaGetSymbolAddress((void**)&csr, g_csr);
    cudaGetSymbolAddress((void**)&blk, g_blk);
    cudaGetSymbolAddress((void**)&wt,  g_wt);

    cudaFuncSetAttribute(fused_layer,
                         cudaFuncAttributeMaxDynamicSharedMemorySize,
                         GEMM_SMEM);

    int nb_scan = (N + SCAN_BLK - 1) / SCAN_BLK;

    // ---- Weight prep + CSR build (once; reused by both layers) ----
    prep_weights<<<(16384 + 255) / 256, 256>>>(Wl1, Wr1, Wl2, Wr2);
    zero_int_kernel<<<(N + 255) / 256, 256>>>(cnt, N);
    hist_kernel<<<(E + 255) / 256, 256>>>(ei, cnt, E);
    scan_k1<<<nb_scan, 256>>>(cnt, off, blk, N);
    scan_k2<<<1, MAX_SCAN_BLKS>>>(blk, nb_scan);
    scan_k3<<<(N + 255) / 256, 256>>>(off, blk, pos, N);
    fill_kernel<<<(E + 255) / 256, 256>>>(ei, pos, csr, E);

    int tb = (N + 127) / 128;

    // ---- Layer 1: aggregate(x) + transform -> h ----
    fused_layer<<<tb, 256, GEMM_SMEM>>>(x, off, cnt, csr, wt, bl1, h, N, 1);

    // ---- Layer 2: aggregate(h) + transform -> out ----
    fused_layer<<<tb, 256, GEMM_SMEM>>>(h, off, cnt, csr, wt + 4 * 4096,
                                        bl2, out, N, 0);
}

// round 8
// speedup vs baseline: 1.2699x; 1.2699x over previous
#include <cuda_runtime.h>
#include <cuda_bf16.h>
#include <cstdint>

#define MAX_N 100000
#define MAX_E 1250000
#define D 64
#define SCAN_BLK 2048
#define MAX_SCAN_BLKS 64

// ---------------- GEMM smem layout (bytes) ----------------
#define SM_AMH  0
#define SM_AML  18432
#define SM_AXH  36864
#define SM_AXL  55296
#define SM_B    73728
#define SM_BIAS 110592
#define GEMM_SMEM 110848
#define APAD 144   // bytes per padded A/B row

// Scratch (device globals; no allocation allowed).
__device__ float g_mean[MAX_N * D];
__device__ float g_h[MAX_N * D];
__device__ int   g_cnt[MAX_N];
__device__ int   g_off[MAX_N];   // after fill: END pointer per node
__device__ int   g_csr[MAX_E];
__device__ int   g_blk[MAX_SCAN_BLKS];
__device__ unsigned short g_wt[2][4 * 4096];

// ---------------------------------------------------------------------------
__device__ __forceinline__ uint32_t smem_u32(const void* p) {
    uint32_t a;
    asm("{ .reg .u64 t; cvta.to.shared.u64 t, %1; cvt.u32.u64 %0, t; }"
        : "=r"(a) : "l"(p));
    return a;
}
__device__ __forceinline__ void ldsm_x4(uint32_t& r0, uint32_t& r1,
                                        uint32_t& r2, uint32_t& r3,
                                        uint32_t addr) {
    asm volatile("ldmatrix.sync.aligned.m8n8.x4.shared.b16 {%0,%1,%2,%3}, [%4];"
                 : "=r"(r0), "=r"(r1), "=r"(r2), "=r"(r3) : "r"(addr));
}
__device__ __forceinline__ void mma_bf16(float* c, const uint32_t* a,
                                         uint32_t b0, uint32_t b1) {
    asm volatile("mma.sync.aligned.m16n8k16.row.col.f32.bf16.bf16.f32 "
                 "{%0,%1,%2,%3}, {%4,%5,%6,%7}, {%8,%9}, {%0,%1,%2,%3};"
                 : "+f"(c[0]), "+f"(c[1]), "+f"(c[2]), "+f"(c[3])
                 : "r"(a[0]), "r"(a[1]), "r"(a[2]), "r"(a[3]),
                   "r"(b0), "r"(b1));
}
__device__ __forceinline__ void split2(float v, unsigned short& h, unsigned short& l) {
    __nv_bfloat16 hb = __float2bfloat16(v);
    float r = v - __bfloat162float(hb);
    __nv_bfloat16 lb = __float2bfloat16(r);
    h = *(unsigned short*)&hb;
    l = *(unsigned short*)&lb;
}
__device__ __forceinline__ uint2 pack_hi4(unsigned short h0, unsigned short h1,
                                          unsigned short h2, unsigned short h3) {
    return make_uint2((uint32_t)h0 | ((uint32_t)h1 << 16),
                      (uint32_t)h2 | ((uint32_t)h3 << 16));
}

// ---------------------------------------------------------------------------
// CSR build
// ---------------------------------------------------------------------------
__global__ void zero_int_kernel(int* __restrict__ p, int n) {
    int i = blockIdx.x * blockDim.x + threadIdx.x;
    if (i < n) p[i] = 0;
}
__global__ void hist_kernel(const int* __restrict__ ei, int* __restrict__ cnt, int E) {
    int e = blockIdx.x * blockDim.x + threadIdx.x;
    if (e < E) atomicAdd(&cnt[ei[E + e]], 1);
}
__global__ __launch_bounds__(256)
void scan_k1(const int* __restrict__ cnt, int* __restrict__ off,
             int* __restrict__ blk, int n) {
    __shared__ int warp_excl[8];
    int t = threadIdx.x;
    int lane = t & 31, w = t >> 5;
    int base = blockIdx.x * SCAN_BLK + t * 8;
    int v[8];
    int s = 0;
#pragma unroll
    for (int q = 0; q < 8; q++) {
        int idx = base + q;
        v[q] = (idx < n) ? cnt[idx] : 0;
        s += v[q];
    }
    int ps = s;
#pragma unroll
    for (int d = 1; d < 32; d <<= 1) {
        int o = __shfl_up_sync(0xffffffffu, ps, d);
        if (lane >= d) ps += o;
    }
    if (lane == 31) warp_excl[w] = ps;
    __syncthreads();
    if (w == 0 && lane < 8) {
        int ws = warp_excl[lane];
        int pw = ws;
#pragma unroll
        for (int d = 1; d < 8; d <<= 1) {
            int o = __shfl_up_sync(0xffu, pw, d);
            if (lane >= d) pw += o;
        }
        warp_excl[lane] = pw - ws;
    }
    __syncthreads();
    int excl = warp_excl[w] + (ps - s);
    int run = excl;
#pragma unroll
    for (int q = 0; q < 8; q++) {
        int idx = base + q;
        if (idx < n) off[idx] = run;
        run += v[q];
    }
    if (t == 255) blk[blockIdx.x] = excl + s;
}
__global__ void scan_k2(int* __restrict__ blk, int nb) {
    __shared__ int sm[MAX_SCAN_BLKS];
    int t = threadIdx.x;
    int v = (t < nb) ? blk[t] : 0;
    sm[t] = v;
    __syncthreads();
    for (int d = 1; d < MAX_SCAN_BLKS; d <<= 1) {
        int o = (t >= d) ? sm[t - d] : 0;
        __syncthreads();
        sm[t] += o;
        __syncthreads();
    }
    if (t < nb) blk[t] = sm[t] - v;
}
// Add block offsets into off (start pointers, ready for fill's atomic bump).
__global__ void scan_k3(int* __restrict__ off, const int* __restrict__ blk, int n) {
    int i = blockIdx.x * blockDim.x + threadIdx.x;
    if (i < n) off[i] += blk[i >> 11];
}
// fill bumps off directly: afterwards off[v] = end pointer of node v.
__global__ void fill_kernel(const int* __restrict__ ei, int* __restrict__ off,
                            int* __restrict__ csr, int E) {
    int e = blockIdx.x * blockDim.x + threadIdx.x;
    if (e < E) {
        int dst = ei[E + e];
        int p = atomicAdd(&off[dst], 1);
        csr[p] = ei[e];
    }
}

// ---------------------------------------------------------------------------
// Aggregate: mean[node] = sum(x[csr[s..e)]) / max(cnt,1),
// where e = off_end[node], s = e - cnt[node]. 16 threads/node, unroll 4.
// ---------------------------------------------------------------------------
__global__ __launch_bounds__(256)
void aggregate_kernel(const float4* __restrict__ x4,
                      const int* __restrict__ off_end,
                      const int* __restrict__ cnt,
                      const int* __restrict__ csr,
                      float4* __restrict__ mean4, int n) {
    int tid = blockIdx.x * blockDim.x + threadIdx.x;
    int node = tid >> 4;
    if (node >= n) return;
    int j = tid & 15;
    int e = off_end[node];
    int c = cnt[node];
    int s = e - c;

    float4 a0 = make_float4(0.f, 0.f, 0.f, 0.f);
    float4 a1 = a0, a2 = a0, a3 = a0;
    int i = s;
    for (; i + 4 <= e; i += 4) {
        int s0 = csr[i], s1 = csr[i + 1], s2 = csr[i + 2], s3 = csr[i + 3];
        float4 v0 = x4[(size_t)s0 * 16 + j];
        float4 v1 = x4[(size_t)s1 * 16 + j];
        float4 v2 = x4[(size_t)s2 * 16 + j];
        float4 v3 = x4[(size_t)s3 * 16 + j];
        a0.x += v0.x; a0.y += v0.y; a0.z += v0.z; a0.w += v0.w;
        a1.x += v1.x; a1.y += v1.y; a1.z += v1.z; a1.w += v1.w;
        a2.x += v2.x; a2.y += v2.y; a2.z += v2.z; a2.w += v2.w;
        a3.x += v3.x; a3.y += v3.y; a3.z += v3.z; a3.w += v3.w;
    }
    for (; i < e; i++) {
        float4 v = x4[(size_t)csr[i] * 16 + j];
        a0.x += v.x; a0.y += v.y; a0.z += v.z; a0.w += v.w;
    }
    float inv = 1.0f / fmaxf((float)c, 1.0f);
    a0.x = (a0.x + a1.x + a2.x + a3.x) * inv;
    a0.y = (a0.y + a1.y + a2.y + a3.y) * inv;
    a0.z = (a0.z + a1.z + a2.z + a3.z) * inv;
    a0.w = (a0.w + a1.w + a2.w + a3.w) * inv;
    mean4[(size_t)node * 16 + j] = a0;
}

// ---------------------------------------------------------------------------
// Weight prep
// ---------------------------------------------------------------------------
__global__ void prep_weights(const float* __restrict__ Wl1,
                             const float* __restrict__ Wr1,
                             const float* __restrict__ Wl2,
                             const float* __restrict__ Wr2) {
    int i = blockIdx.x * blockDim.x + threadIdx.x;
    if (i >= 2 * 2 * 64 * 64) return;
    int k = i & 63;
    int nn = (i >> 6) & 63;
    int mat = (i >> 12) & 1;
    int layer = (i >> 13) & 1;
    const float* W = (layer == 0) ? (mat == 0 ? Wl1 : Wr1)
                                  : (mat == 0 ? Wl2 : Wr2);
    float v = W[k * 64 + nn];
    unsigned short h, l;
    split2(v, h, l);
    g_wt[layer][(mat * 2 + 0) * 4096 + nn * 64 + k] = h;
    g_wt[layer][(mat * 2 + 1) * 4096 + nn * 64 + k] = l;
}

// ---------------------------------------------------------------------------
// Tensor-core transform via mma.sync m16n8k16 bf16 (3-product split).
// CTA = 128 nodes, 256 threads. A staging now fully coalesced (linear map).
// ---------------------------------------------------------------------------
__global__ __launch_bounds__(256)
void gemm_transform(const float* __restrict__ xin,
                    const float* __restrict__ mean,
                    const unsigned short* __restrict__ wt,
                    const float* __restrict__ bl,
                    float* __restrict__ out,
                    int n, int do_relu) {
    extern __shared__ char smem[];
    uint32_t sb = smem_u32(smem);
    int t = threadIdx.x;
    int wid = t >> 5;
    int lane = t & 31;
    int base = blockIdx.x * 128;

    // --- Stage weights + bias ---
    {
        int mat = t >> 6;
        int nrow = t & 63;
        const uint4* src = (const uint4*)(wt + mat * 4096 + nrow * 64);
        uint4* dst = (uint4*)(smem + SM_B + mat * 9216 + nrow * APAD);
#pragma unroll
        for (int q = 0; q < 8; q++) dst[q] = src[q];
    }
    if (t < 64) ((float*)(smem + SM_BIAS))[t] = bl[t];

    // --- Stage A (coalesced): idx = t + pass*256 over 2048 float4 chunks ---
    {
        const float4* mr = (const float4*)mean;
        const float4* xr = (const float4*)xin;
#pragma unroll
        for (int pass = 0; pass < 8; pass++) {
            int idx = t + pass * 256;
            int row = idx >> 4;
            int j = idx & 15;
            int node = base + row;
            bool valid = node < n;
            float4 mv = valid ? mr[(size_t)node * 16 + j]
                              : make_float4(0.f, 0.f, 0.f, 0.f);
            float4 xv = valid ? xr[(size_t)node * 16 + j]
                              : make_float4(0.f, 0.f, 0.f, 0.f);
            int boff = row * APAD + j * 8;
            unsigned short h0, h1, h2, h3, l0, l1, l2, l3;
            split2(mv.x, h0, l0); split2(mv.y, h1, l1);
            split2(mv.z, h2, l2); split2(mv.w, h3, l3);
            *(uint2*)(smem + SM_AMH + boff) = pack_hi4(h0, h1, h2, h3);
            *(uint2*)(smem + SM_AML + boff) = pack_hi4(l0, l1, l2, l3);
            split2(xv.x, h0, l0); split2(xv.y, h1, l1);
            split2(xv.z, h2, l2); split2(xv.w, h3, l3);
            *(uint2*)(smem + SM_AXH + boff) = pack_hi4(h0, h1, h2, h3);
            *(uint2*)(smem + SM_AXL + boff) = pack_hi4(l0, l1, l2, l3);
        }
    }
    __syncthreads();

    // --- MMA mainloop: 6 products x 4 ksteps x 8 n-tiles ---
    const uint32_t paOff[6] = {SM_AMH, SM_AMH, SM_AML, SM_AXH, SM_AXH, SM_AXL};
    const uint32_t pbOff[6] = {SM_B + 0 * 9216, SM_B + 1 * 9216, SM_B + 0 * 9216,
                               SM_B + 2 * 9216, SM_B + 3 * 9216, SM_B + 2 * 9216};

    int wrow = wid * 16;
    uint32_t a_row = wrow + (lane & 7) + ((lane >> 3) & 1) * 8;
    uint32_t a_colb = ((lane >> 4) * 8) * 2;
    uint32_t a_base_off = a_row * APAD + a_colb;
    uint32_t b_row = ((lane >> 4) * 8 + (lane & 7));
    uint32_t b_colb = (((lane >> 3) & 1) * 8) * 2;
    uint32_t b_base_off = b_row * APAD + b_colb;

    float acc[8][4];
#pragma unroll
    for (int jj = 0; jj < 8; jj++)
#pragma unroll
        for (int q = 0; q < 4; q++) acc[jj][q] = 0.f;

#pragma unroll
    for (int p = 0; p < 6; p++) {
        uint32_t aBase = sb + paOff[p] + a_base_off;
        uint32_t bBase = sb + pbOff[p] + b_base_off;
#pragma unroll
        for (int k = 0; k < 4; k++) {
            uint32_t a[4];
            ldsm_x4(a[0], a[1], a[2], a[3], aBase + k * 32);
#pragma unroll
            for (int jj = 0; jj < 4; jj++) {
                uint32_t b0, b1, b2, b3;
                ldsm_x4(b0, b1, b2, b3, bBase + jj * 16 * APAD + k * 32);
                mma_bf16(acc[2 * jj],     a, b0, b1);
                mma_bf16(acc[2 * jj + 1], a, b2, b3);
            }
        }
    }

    // --- Epilogue ---
    const float* bias = (const float*)(smem + SM_BIAS);
    int r0 = base + wrow + (lane >> 2);
    int r1 = r0 + 8;
    int ctig = 2 * (lane & 3);
#pragma unroll
    for (int jj = 0; jj < 8; jj++) {
        int col = 8 * jj + ctig;
        float bx = bias[col], by = bias[col + 1];
        float2 v0 = make_float2(acc[jj][0] + bx, acc[jj][1] + by);
        float2 v1 = make_float2(acc[jj][2] + bx, acc[jj][3] + by);
        if (do_relu) {
            v0.x = fmaxf(v0.x, 0.f); v0.y = fmaxf(v0.y, 0.f);
            v1.x = fmaxf(v1.x, 0.f); v1.y = fmaxf(v1.y, 0.f);
        }
        if (r0 < n) *(float2*)&out[(size_t)r0 * 64 + col] = v0;
        if (r1 < n) *(float2*)&out[(size_t)r1 * 64 + col] = v1;
    }
}

// ---------------------------------------------------------------------------
extern "C" void kernel_launch(void* const* d_in, const int* in_sizes, int n_in,
                              void* d_out, int out_size) {
    const float* x   = (const float*)d_in[0];
    const int*   ei  = (const int*)d_in[1];
    const float* Wl1 = (const float*)d_in[2];
    const float* bl1 = (const float*)d_in[3];
    const float* Wr1 = (const float*)d_in[4];
    const float* Wl2 = (const float*)d_in[5];
    const float* bl2 = (const float*)d_in[6];
    const float* Wr2 = (const float*)d_in[7];
    float* out = (float*)d_out;

    int N = in_sizes[0] / D;   // 100000
    int E = in_sizes[1] / 2;   // 1250000

    float *mean, *h;
    int *cnt, *off, *csr, *blk;
    unsigned short* wt;
    cudaGetSymbolAddress((void**)&mean, g_mean);
    cudaGetSymbolAddress((void**)&h,    g_h);
    cudaGetSymbolAddress((void**)&cnt,  g_cnt);
    cudaGetSymbolAddress((void**)&off,  g_off);
    cudaGetSymbolAddress((void**)&csr,  g_csr);
    cudaGetSymbolAddress((void**)&blk,  g_blk);
    cudaGetSymbolAddress((void**)&wt,   g_wt);

    cudaFuncSetAttribute(gemm_transform,
                         cudaFuncAttributeMaxDynamicSharedMemorySize,
                         GEMM_SMEM);

    int nb_scan = (N + SCAN_BLK - 1) / SCAN_BLK;

    // ---- Weight prep + CSR build ----
    prep_weights<<<(16384 + 255) / 256, 256>>>(Wl1, Wr1, Wl2, Wr2);
    zero_int_kernel<<<(N + 255) / 256, 256>>>(cnt, N);
    hist_kernel<<<(E + 255) / 256, 256>>>(ei, cnt, E);
    scan_k1<<<nb_scan, 256>>>(cnt, off, blk, N);
    scan_k2<<<1, MAX_SCAN_BLKS>>>(blk, nb_scan);
    scan_k3<<<(N + 255) / 256, 256>>>(off, blk, N);
    fill_kernel<<<(E + 255) / 256, 256>>>(ei, off, csr, E);
    // off is now END pointers; aggregate uses [off - cnt, off).

    int ab = (N * 16 + 255) / 256;
    int tb = (N + 127) / 128;

    // ---- Layer 1 ----
    aggregate_kernel<<<ab, 256>>>((const float4*)x, off, cnt, csr,
                                  (float4*)mean, N);
    gemm_transform<<<tb, 256, GEMM_SMEM>>>(x, mean, wt, bl1, h, N, 1);

    // ---- Layer 2 ----
    aggregate_kernel<<<ab, 256>>>((const float4*)h, off, cnt, csr,
                                  (float4*)mean, N);
    gemm_transform<<<tb, 256, GEMM_SMEM>>>(h, mean, wt + 4 * 4096, bl2, out, N, 0);
}